// round 1
// baseline (speedup 1.0000x reference)
#include <cuda_runtime.h>

// Problem constants
#define N_TOK 8192
#define DIM   1024

// ---------------- scratch (device globals: no allocation allowed) ----------
__device__ float g_Q[N_TOK * DIM];
__device__ float g_K[N_TOK * DIM];
__device__ float g_V[N_TOK * DIM];
__device__ float g_S[(size_t)N_TOK * N_TOK];
__device__ float g_rowinv[N_TOK];

// ---------------- packed fp32x2 FMA (sm_103a) ------------------------------
__device__ __forceinline__ float2 ffma2(float2 a, float2 b, float2 c) {
    unsigned long long ua = *reinterpret_cast<unsigned long long*>(&a);
    unsigned long long ub = *reinterpret_cast<unsigned long long*>(&b);
    unsigned long long uc = *reinterpret_cast<unsigned long long*>(&c);
    unsigned long long ud;
    asm("fma.rn.f32x2 %0, %1, %2, %3;" : "=l"(ud) : "l"(ua), "l"(ub), "l"(uc));
    return *reinterpret_cast<float2*>(&ud);
}

// ---------------- SGEMM: C[M,N] = alpha * A[M,K] @ op(B) -------------------
// TRANS_B=false: B is [K,N] row-major.  TRANS_B=true: B is [N,K] row-major (B^T used).
// If row_scale != nullptr, C row r is additionally scaled by row_scale[r].
// Tiles: 128x128x16, 256 threads, 8x8 per thread via f32x2 packed FMA.
template<bool TRANS_B>
__global__ __launch_bounds__(256, 2)
void sgemm_f32x2(const float* __restrict__ A, const float* __restrict__ B,
                 float* __restrict__ C, int M, int N, int K,
                 float alpha, const float* __restrict__ row_scale)
{
    __shared__ float As[16][128];   // As[k][m]
    __shared__ float Bs[16][128];   // Bs[k][n]

    const int tid = threadIdx.x;
    const int tx  = tid & 15;          // 0..15 -> col group (8 cols)
    const int ty  = tid >> 4;          // 0..15 -> row group (8 rows)
    const int rowBase = blockIdx.y * 128;
    const int colBase = blockIdx.x * 128;

    // transposed-store load mapping (used for A always, B when TRANS_B)
    const int a_r  = tid >> 2;         // 0..63
    const int a_c4 = (tid & 3) << 2;   // 0,4,8,12

    // direct-store load mapping (B when !TRANS_B)
    const int bn_r = tid >> 5;         // 0..7
    const int bn_c = (tid & 31) << 2;  // 0..124

    float2 acc[4][8];
    #pragma unroll
    for (int i = 0; i < 4; i++)
        #pragma unroll
        for (int j = 0; j < 8; j++) acc[i][j] = make_float2(0.f, 0.f);

    for (int k0 = 0; k0 < K; k0 += 16) {
        // ---- load A tile (transpose into As[k][m]) ----
        #pragma unroll
        for (int h = 0; h < 2; h++) {
            int r = a_r + h * 64;
            float4 v = *(const float4*)&A[(size_t)(rowBase + r) * K + k0 + a_c4];
            As[a_c4 + 0][r] = v.x; As[a_c4 + 1][r] = v.y;
            As[a_c4 + 2][r] = v.z; As[a_c4 + 3][r] = v.w;
        }
        // ---- load B tile ----
        if (TRANS_B) {
            #pragma unroll
            for (int h = 0; h < 2; h++) {
                int r = a_r + h * 64;
                float4 v = *(const float4*)&B[(size_t)(colBase + r) * K + k0 + a_c4];
                Bs[a_c4 + 0][r] = v.x; Bs[a_c4 + 1][r] = v.y;
                Bs[a_c4 + 2][r] = v.z; Bs[a_c4 + 3][r] = v.w;
            }
        } else {
            #pragma unroll
            for (int h = 0; h < 2; h++) {
                int r = bn_r + h * 8;
                float4 v = *(const float4*)&B[(size_t)(k0 + r) * N + colBase + bn_c];
                *(float4*)&Bs[r][bn_c] = v;
            }
        }
        __syncthreads();

        // ---- compute ----
        #pragma unroll
        for (int kk = 0; kk < 16; kk++) {
            float4 a0 = *(const float4*)&As[kk][ty * 8];
            float4 a1 = *(const float4*)&As[kk][ty * 8 + 4];
            float2 a2[4] = { make_float2(a0.x, a0.y), make_float2(a0.z, a0.w),
                             make_float2(a1.x, a1.y), make_float2(a1.z, a1.w) };
            float4 b0 = *(const float4*)&Bs[kk][tx * 8];
            float4 b1 = *(const float4*)&Bs[kk][tx * 8 + 4];
            float bv[8] = { b0.x, b0.y, b0.z, b0.w, b1.x, b1.y, b1.z, b1.w };
            #pragma unroll
            for (int j = 0; j < 8; j++) {
                float2 bd = make_float2(bv[j], bv[j]);
                #pragma unroll
                for (int i = 0; i < 4; i++)
                    acc[i][j] = ffma2(a2[i], bd, acc[i][j]);
            }
        }
        __syncthreads();
    }

    // ---- epilogue ----
    #pragma unroll
    for (int i = 0; i < 4; i++) {
        int r0 = rowBase + ty * 8 + 2 * i;
        float sc0 = alpha, sc1 = alpha;
        if (row_scale) { sc0 *= row_scale[r0]; sc1 *= row_scale[r0 + 1]; }
        float o0[8], o1[8];
        #pragma unroll
        for (int j = 0; j < 8; j++) {
            o0[j] = acc[i][j].x * sc0;
            o1[j] = acc[i][j].y * sc1;
        }
        float* c0 = &C[(size_t)r0 * N + colBase + tx * 8];
        float* c1 = c0 + N;
        *(float4*)(c0)     = make_float4(o0[0], o0[1], o0[2], o0[3]);
        *(float4*)(c0 + 4) = make_float4(o0[4], o0[5], o0[6], o0[7]);
        *(float4*)(c1)     = make_float4(o1[0], o1[1], o1[2], o1[3]);
        *(float4*)(c1 + 4) = make_float4(o1[4], o1[5], o1[6], o1[7]);
    }
}

// ---------------- row softmax over S[N_TOK, N_TOK] -------------------------
// Writes exp(s - rowmax) in place and 1/rowsum into rowinv.
__device__ __forceinline__ float warpMax(float v) {
    #pragma unroll
    for (int o = 16; o; o >>= 1) v = fmaxf(v, __shfl_xor_sync(0xffffffffu, v, o));
    return v;
}
__device__ __forceinline__ float warpSum(float v) {
    #pragma unroll
    for (int o = 16; o; o >>= 1) v += __shfl_xor_sync(0xffffffffu, v, o);
    return v;
}

__global__ __launch_bounds__(256)
void softmax_rows(float* __restrict__ S, float* __restrict__ rowinv)
{
    const int n4 = N_TOK / 4;
    float4* p = reinterpret_cast<float4*>(S + (size_t)blockIdx.x * N_TOK);
    const int tid = threadIdx.x;
    __shared__ float sh[8];

    // pass 1: row max
    float m = -3.4e38f;
    for (int i = tid; i < n4; i += 256) {
        float4 v = p[i];
        m = fmaxf(m, fmaxf(fmaxf(v.x, v.y), fmaxf(v.z, v.w)));
    }
    m = warpMax(m);
    if ((tid & 31) == 0) sh[tid >> 5] = m;
    __syncthreads();
    if (tid == 0) {
        float t = sh[0];
        #pragma unroll
        for (int w = 1; w < 8; w++) t = fmaxf(t, sh[w]);
        sh[0] = t;
    }
    __syncthreads();
    m = sh[0];
    __syncthreads();

    // pass 2: exp + sum
    float s = 0.f;
    for (int i = tid; i < n4; i += 256) {
        float4 v = p[i];
        v.x = __expf(v.x - m); v.y = __expf(v.y - m);
        v.z = __expf(v.z - m); v.w = __expf(v.w - m);
        s += (v.x + v.y) + (v.z + v.w);
        p[i] = v;
    }
    s = warpSum(s);
    if ((tid & 31) == 0) sh[tid >> 5] = s;
    __syncthreads();
    if (tid == 0) {
        float t = 0.f;
        #pragma unroll
        for (int w = 0; w < 8; w++) t += sh[w];
        rowinv[blockIdx.x] = 1.0f / t;
    }
}

// ---------------- launch ----------------------------------------------------
extern "C" void kernel_launch(void* const* d_in, const int* in_sizes, int n_in,
                              void* d_out, int out_size)
{
    const float* x  = (const float*)d_in[0];
    const float* Wq = (const float*)d_in[1];
    const float* Wk = (const float*)d_in[2];
    const float* Wv = (const float*)d_in[3];
    float* out = (float*)d_out;

    float *Q, *K, *V, *S, *Rinv;
    cudaGetSymbolAddress((void**)&Q, g_Q);
    cudaGetSymbolAddress((void**)&K, g_K);
    cudaGetSymbolAddress((void**)&V, g_V);
    cudaGetSymbolAddress((void**)&S, g_S);
    cudaGetSymbolAddress((void**)&Rinv, g_rowinv);

    dim3 blk(256);
    dim3 gProj(DIM / 128, N_TOK / 128);      // (8, 64)
    dim3 gScores(N_TOK / 128, N_TOK / 128);  // (64, 64)

    // Reference swaps names: q = x @ Wk, k = x @ Wq, v = x @ Wv
    sgemm_f32x2<false><<<gProj, blk>>>(x, Wk, Q, N_TOK, DIM, DIM, 1.f, nullptr);
    sgemm_f32x2<false><<<gProj, blk>>>(x, Wq, K, N_TOK, DIM, DIM, 1.f, nullptr);
    sgemm_f32x2<false><<<gProj, blk>>>(x, Wv, V, N_TOK, DIM, DIM, 1.f, nullptr);

    // S = Q @ K^T / sqrt(1024)
    sgemm_f32x2<true><<<gScores, blk>>>(Q, K, S, N_TOK, N_TOK, DIM, 0.03125f, nullptr);

    // softmax rows (exp in place + 1/rowsum)
    softmax_rows<<<N_TOK, 256>>>(S, Rinv);

    // out = diag(rowinv) * P @ V
    sgemm_f32x2<false><<<gProj, blk>>>(S, V, out, N_TOK, DIM, N_TOK, 1.f, Rinv);
}

// round 3
// speedup vs baseline: 3.6690x; 3.6690x over previous
#include <cuda_runtime.h>
#include <cstdint>

#define N_TOK 8192
#define DIM   1024

// ---- mma tile config ----
#define BM 128
#define BN 128
#define BK 16
#define NST 4
#define RS 20                       // padded row stride in floats (80 B)
#define OPBYTES (128 * RS * 4)      // 10240 B per operand per stage
#define SS (2 * OPBYTES)            // 20480 B per stage (A|B interleaved)
#define SMEM_BYTES (NST * SS)       // 81920 B

// ---- scratch (device globals; no allocation allowed) ----
__device__ float g_X [N_TOK * DIM];
__device__ float g_Q [N_TOK * DIM];
__device__ float g_K [N_TOK * DIM];
__device__ float g_V [N_TOK * DIM];
__device__ float g_VT[N_TOK * DIM];
__device__ float g_WT[3][DIM * DIM];
__device__ float g_S [(size_t)N_TOK * N_TOK];
__device__ float g_rinv[N_TOK];

// =================== helpers ===================
__device__ __forceinline__ float tf32r(float x) {
    uint32_t u;
    asm("cvt.rna.tf32.f32 %0, %1;" : "=r"(u) : "f"(x));
    return __uint_as_float(u);
}
__device__ __forceinline__ uint32_t smem_u32(const void* p) {
    uint32_t a;
    asm("{ .reg .u64 t; cvta.to.shared.u64 t, %1; cvt.u32.u64 %0, t; }" : "=r"(a) : "l"(p));
    return a;
}
__device__ __forceinline__ void cp16(uint32_t dst, const void* src) {
    asm volatile("cp.async.cg.shared.global [%0], [%1], 16;" :: "r"(dst), "l"(src));
}
__device__ __forceinline__ void cp_commit() {
    asm volatile("cp.async.commit_group;" ::: "memory");
}
__device__ __forceinline__ void cp_wait2() {
    asm volatile("cp.async.wait_group 2;" ::: "memory");
}
__device__ __forceinline__ void ldsm4(uint32_t* r, uint32_t addr) {
    asm volatile("ldmatrix.sync.aligned.m8n8.x4.shared.b16 {%0,%1,%2,%3}, [%4];"
                 : "=r"(r[0]), "=r"(r[1]), "=r"(r[2]), "=r"(r[3]) : "r"(addr));
}
__device__ __forceinline__ void mma_tf32(float* c, const uint32_t* a, uint32_t b0, uint32_t b1) {
    asm volatile(
        "mma.sync.aligned.m16n8k8.row.col.f32.tf32.tf32.f32 "
        "{%0,%1,%2,%3}, {%4,%5,%6,%7}, {%8,%9}, {%0,%1,%2,%3};"
        : "+f"(c[0]), "+f"(c[1]), "+f"(c[2]), "+f"(c[3])
        : "r"(a[0]), "r"(a[1]), "r"(a[2]), "r"(a[3]), "r"(b0), "r"(b1));
}

// =================== tf32 mma.sync GEMM ===================
// C[M,N] = f(alpha * A[M,K] @ B[N,K]^T)
// MODE 0: C = alpha*acc * row_scale[r]       (PV; final output)
// MODE 1: C = tf32round(acc)                 (projections; feeds next GEMM)
// MODE 2: C = tf32round(exp(alpha*acc))      (scores -> probabilities)
template<int MODE>
__global__ __launch_bounds__(256, 2)
void gemm_mma(const float* __restrict__ A, const float* __restrict__ B,
              float* __restrict__ C, int M, int N, int K,
              float alpha, const float* __restrict__ row_scale)
{
    extern __shared__ char smraw[];
    const uint32_t sbase = smem_u32(smraw);
    const int tid  = threadIdx.x;
    const int wid  = tid >> 5, lane = tid & 31;
    const int wm   = wid & 1, wn = wid >> 1;
    const int rowBase = blockIdx.y * BM;
    const int colBase = blockIdx.x * BN;
    const int nk = K / BK;

    // ---- gmem load setup (4 x 16B cp.async per thread per stage) ----
    const int gr = tid >> 2, gk = (tid & 3) << 2;
    const float* gA = A + (size_t)(rowBase + gr) * K + gk;
    const float* gB = B + (size_t)(colBase + gr) * K + gk;
    const size_t rowHop = (size_t)64 * K;
    const uint32_t dA = (uint32_t)(gr * RS + gk) * 4;
    const uint32_t dB = OPBYTES + dA;

    // ---- ldmatrix per-thread offsets (within one stage) ----
    const int quad = lane >> 3, lr = lane & 7;
    uint32_t aOff[4], bOff[2];
    #pragma unroll
    for (int mt = 0; mt < 4; mt++) {
        int r = wm * 64 + mt * 16 + (quad & 1) * 8 + lr;
        aOff[mt] = (uint32_t)(r * RS + (quad >> 1) * 4) * 4;
    }
    #pragma unroll
    for (int p = 0; p < 2; p++) {
        int r = wn * 32 + p * 16 + (quad >> 1) * 8 + lr;
        bOff[p] = OPBYTES + (uint32_t)(r * RS + (quad & 1) * 4) * 4;
    }

    float acc[4][4][4];
    #pragma unroll
    for (int i = 0; i < 4; i++)
        #pragma unroll
        for (int j = 0; j < 4; j++)
            #pragma unroll
            for (int e = 0; e < 4; e++) acc[i][j][e] = 0.f;

    // ---- prologue: fill NST-1 stages ----
    #pragma unroll
    for (int s = 0; s < NST - 1; s++) {
        const uint32_t d = sbase + s * SS;
        const int k0 = s * BK;
        cp16(d + dA,          gA + k0);
        cp16(d + dA + 64*RS*4, gA + rowHop + k0);
        cp16(d + dB,          gB + k0);
        cp16(d + dB + 64*RS*4, gB + rowHop + k0);
        cp_commit();
    }

    // ---- main loop ----
    for (int it = 0; it < nk; it++) {
        cp_wait2();
        __syncthreads();

        // issue loads for stage it+NST-1 (overlaps with compute below)
        if (it + NST - 1 < nk) {
            const uint32_t d = sbase + ((it + NST - 1) & (NST - 1)) * SS;
            const int k0 = (it + NST - 1) * BK;
            cp16(d + dA,          gA + k0);
            cp16(d + dA + 64*RS*4, gA + rowHop + k0);
            cp16(d + dB,          gB + k0);
            cp16(d + dB + 64*RS*4, gB + rowHop + k0);
        }
        cp_commit();

        const uint32_t st = sbase + (it & (NST - 1)) * SS;
        #pragma unroll
        for (int kk = 0; kk < 2; kk++) {
            const uint32_t ko = kk * 32;   // k += 8 -> 32 bytes
            uint32_t a[4][4], b[2][4];
            #pragma unroll
            for (int mt = 0; mt < 4; mt++) ldsm4(a[mt], st + aOff[mt] + ko);
            #pragma unroll
            for (int p = 0; p < 2; p++)    ldsm4(b[p],  st + bOff[p] + ko);
            #pragma unroll
            for (int mt = 0; mt < 4; mt++)
                #pragma unroll
                for (int p = 0; p < 2; p++) {
                    mma_tf32(acc[mt][2*p],   a[mt], b[p][0], b[p][1]);
                    mma_tf32(acc[mt][2*p+1], a[mt], b[p][2], b[p][3]);
                }
        }
        __syncthreads();
    }

    // ---- epilogue ----
    const int g = lane >> 2, tg = lane & 3;
    #pragma unroll
    for (int mt = 0; mt < 4; mt++) {
        const int r0 = rowBase + wm * 64 + mt * 16 + g;
        float sc0 = 1.f, sc1 = 1.f;
        if (MODE == 0) {
            sc0 = alpha * row_scale[r0];
            sc1 = alpha * row_scale[r0 + 8];
        }
        #pragma unroll
        for (int nt = 0; nt < 4; nt++) {
            const int c = colBase + wn * 32 + nt * 8 + tg * 2;
            float v0 = acc[mt][nt][0], v1 = acc[mt][nt][1];
            float v2 = acc[mt][nt][2], v3 = acc[mt][nt][3];
            if (MODE == 0) { v0 *= sc0; v1 *= sc0; v2 *= sc1; v3 *= sc1; }
            if (MODE == 1) { v0 = tf32r(v0); v1 = tf32r(v1); v2 = tf32r(v2); v3 = tf32r(v3); }
            if (MODE == 2) {
                v0 = tf32r(__expf(alpha * v0)); v1 = tf32r(__expf(alpha * v1));
                v2 = tf32r(__expf(alpha * v2)); v3 = tf32r(__expf(alpha * v3));
            }
            *(float2*)&C[(size_t)r0 * N + c]       = make_float2(v0, v1);
            *(float2*)&C[(size_t)(r0 + 8) * N + c] = make_float2(v2, v3);
        }
    }
}

// =================== transpose (+tf32 round): out[C,R] = round(in[R,C]^T) ===================
__global__ void transpose_r(const float* __restrict__ in, float* __restrict__ out, int R, int C)
{
    __shared__ float t[32][33];
    const int c0 = blockIdx.x * 32, r0 = blockIdx.y * 32;
    const int x = threadIdx.x, y = threadIdx.y;
    #pragma unroll
    for (int j = 0; j < 32; j += 8)
        t[y + j][x] = in[(size_t)(r0 + y + j) * C + c0 + x];
    __syncthreads();
    #pragma unroll
    for (int j = 0; j < 32; j += 8)
        out[(size_t)(c0 + y + j) * R + r0 + x] = tf32r(t[x][y + j]);
}

// =================== round-copy x -> xr ===================
__global__ __launch_bounds__(256)
void round_copy(const float* __restrict__ in, float* __restrict__ out, int n4)
{
    int i = blockIdx.x * 256 + threadIdx.x;
    if (i < n4) {
        float4 v = ((const float4*)in)[i];
        v.x = tf32r(v.x); v.y = tf32r(v.y); v.z = tf32r(v.z); v.w = tf32r(v.w);
        ((float4*)out)[i] = v;
    }
}

// =================== row sums of P -> rinv ===================
__global__ __launch_bounds__(256)
void rowsum_inv(const float* __restrict__ P, float* __restrict__ rinv)
{
    const int tid = threadIdx.x;
    const float4* p = (const float4*)(P + (size_t)blockIdx.x * N_TOK);
    float s = 0.f;
    for (int i = tid; i < N_TOK / 4; i += 256) {
        float4 v = p[i];
        s += (v.x + v.y) + (v.z + v.w);
    }
    #pragma unroll
    for (int o = 16; o; o >>= 1) s += __shfl_xor_sync(0xffffffffu, s, o);
    __shared__ float sh[8];
    if ((tid & 31) == 0) sh[tid >> 5] = s;
    __syncthreads();
    if (tid == 0) {
        float t = 0.f;
        #pragma unroll
        for (int w = 0; w < 8; w++) t += sh[w];
        rinv[blockIdx.x] = 1.0f / t;
    }
}

// =================== host ===================
extern "C" void kernel_launch(void* const* d_in, const int* in_sizes, int n_in,
                              void* d_out, int out_size)
{
    const float* x  = (const float*)d_in[0];
    const float* Wq = (const float*)d_in[1];
    const float* Wk = (const float*)d_in[2];
    const float* Wv = (const float*)d_in[3];
    float* out = (float*)d_out;

    float *X, *Q, *K, *V, *VT, *WT, *S, *Rinv;
    cudaGetSymbolAddress((void**)&X,    g_X);
    cudaGetSymbolAddress((void**)&Q,    g_Q);
    cudaGetSymbolAddress((void**)&K,    g_K);
    cudaGetSymbolAddress((void**)&V,    g_V);
    cudaGetSymbolAddress((void**)&VT,   g_VT);
    cudaGetSymbolAddress((void**)&WT,   g_WT);
    cudaGetSymbolAddress((void**)&S,    g_S);
    cudaGetSymbolAddress((void**)&Rinv, g_rinv);
    float* WkT = WT;
    float* WqT = WT + (size_t)DIM * DIM;
    float* WvT = WT + (size_t)2 * DIM * DIM;

    cudaFuncSetAttribute(gemm_mma<0>, cudaFuncAttributeMaxDynamicSharedMemorySize, SMEM_BYTES);
    cudaFuncSetAttribute(gemm_mma<1>, cudaFuncAttributeMaxDynamicSharedMemorySize, SMEM_BYTES);
    cudaFuncSetAttribute(gemm_mma<2>, cudaFuncAttributeMaxDynamicSharedMemorySize, SMEM_BYTES);

    const dim3 tblk(32, 8);

    // prep: round x; transpose+round weights ([in,out] -> [out,in])
    round_copy<<<(N_TOK * DIM / 4 + 255) / 256, 256>>>(x, X, N_TOK * DIM / 4);
    transpose_r<<<dim3(32, 32), tblk>>>(Wk, WkT, DIM, DIM);
    transpose_r<<<dim3(32, 32), tblk>>>(Wq, WqT, DIM, DIM);
    transpose_r<<<dim3(32, 32), tblk>>>(Wv, WvT, DIM, DIM);

    const dim3 gProj(DIM / BN, N_TOK / BM);     // (8, 64)
    const dim3 gScore(N_TOK / BN, N_TOK / BM);  // (64, 64)

    // reference name-swap: q = x@Wk, k = x@Wq, v = x@Wv
    gemm_mma<1><<<gProj, 256, SMEM_BYTES>>>(X, WkT, Q, N_TOK, DIM, DIM, 1.f, nullptr);
    gemm_mma<1><<<gProj, 256, SMEM_BYTES>>>(X, WqT, K, N_TOK, DIM, DIM, 1.f, nullptr);
    gemm_mma<1><<<gProj, 256, SMEM_BYTES>>>(X, WvT, V, N_TOK, DIM, DIM, 1.f, nullptr);

    // V^T for PV GEMM B operand (V already tf32-rounded)
    transpose_r<<<dim3(DIM / 32, N_TOK / 32), tblk>>>(V, VT, N_TOK, DIM);

    // P = round(exp(QK^T / 32)) fused in epilogue
    gemm_mma<2><<<gScore, 256, SMEM_BYTES>>>(Q, K, S, N_TOK, N_TOK, DIM, 0.03125f, nullptr);

    // rinv = 1 / rowsum(P)
    rowsum_inv<<<N_TOK, 256>>>(S, Rinv);

    // out = diag(rinv) * P @ V
    gemm_mma<0><<<gProj, 256, SMEM_BYTES>>>(S, VT, out, N_TOK, DIM, N_TOK, 1.f, Rinv);
}

// round 4
// speedup vs baseline: 6.4104x; 1.7472x over previous
#include <cuda_runtime.h>
#include <cuda_fp16.h>
#include <cstdint>

#define N_TOK 8192
#define DIM   1024

// ---- fp16 mma tile config ----
#define BM 128
#define BN 128
#define BK 32
#define NST 4
#define RSH 40                        // halves per smem row (80 B, conflict-free ldmatrix)
#define OPB (128 * RSH * 2)           // 10240 B per operand per stage
#define SS  (2 * OPB)                 // 20480 B per stage
#define SMEM_BYTES (NST * SS)         // 81920 B

// ---- scratch (device globals; no allocation allowed) ----
__device__ __half g_X [N_TOK * DIM];
__device__ __half g_Q [N_TOK * DIM];
__device__ __half g_K [N_TOK * DIM];
__device__ __half g_V [N_TOK * DIM];
__device__ __half g_VT[N_TOK * DIM];
__device__ __half g_WT[3][DIM * DIM];
__device__ __half g_S [(size_t)N_TOK * N_TOK];
__device__ float  g_rinv[N_TOK];

// =================== helpers ===================
__device__ __forceinline__ uint32_t smem_u32(const void* p) {
    uint32_t a;
    asm("{ .reg .u64 t; cvta.to.shared.u64 t, %1; cvt.u32.u64 %0, t; }" : "=r"(a) : "l"(p));
    return a;
}
__device__ __forceinline__ void cp16(uint32_t dst, const void* src) {
    asm volatile("cp.async.cg.shared.global [%0], [%1], 16;" :: "r"(dst), "l"(src));
}
__device__ __forceinline__ void cp_commit() {
    asm volatile("cp.async.commit_group;" ::: "memory");
}
__device__ __forceinline__ void cp_wait2() {
    asm volatile("cp.async.wait_group 2;" ::: "memory");
}
__device__ __forceinline__ void ldsm4(uint32_t* r, uint32_t addr) {
    asm volatile("ldmatrix.sync.aligned.m8n8.x4.shared.b16 {%0,%1,%2,%3}, [%4];"
                 : "=r"(r[0]), "=r"(r[1]), "=r"(r[2]), "=r"(r[3]) : "r"(addr));
}
__device__ __forceinline__ void mma_f16(float* c, const uint32_t* a, uint32_t b0, uint32_t b1) {
    asm volatile(
        "mma.sync.aligned.m16n8k16.row.col.f32.f16.f16.f32 "
        "{%0,%1,%2,%3}, {%4,%5,%6,%7}, {%8,%9}, {%0,%1,%2,%3};"
        : "+f"(c[0]), "+f"(c[1]), "+f"(c[2]), "+f"(c[3])
        : "r"(a[0]), "r"(a[1]), "r"(a[2]), "r"(a[3]), "r"(b0), "r"(b1));
}

// =================== fp16 mma.sync GEMM ===================
// acc = A[M,K] @ B[N,K]^T   (A,B fp16; acc fp32)
// MODE 0: C fp32 = acc * alpha * row_scale[r]      (PV; final output)
// MODE 1: C fp16 = acc                             (projections)
// MODE 2: C fp16 = exp(alpha * acc)                (scores -> probabilities)
template<int MODE>
__global__ __launch_bounds__(256, 2)
void gemm_h(const __half* __restrict__ A, const __half* __restrict__ B,
            void* __restrict__ Cv, int M, int N, int K,
            float alpha, const float* __restrict__ row_scale)
{
    extern __shared__ char smraw[];
    const uint32_t sbase = smem_u32(smraw);
    const int tid  = threadIdx.x;
    const int wid  = tid >> 5, lane = tid & 31;
    const int wm   = wid & 1, wn = wid >> 1;
    const int rowBase = blockIdx.y * BM;
    const int colBase = blockIdx.x * BN;
    const int nk = K / BK;

    // ---- gmem -> smem: 64B rows (32 halves); 2 x 16B per operand per thread ----
    const int gr = tid >> 2;                 // 0..63
    const int gs = (tid & 3) * 8;            // half offset within row
    const __half* gA = A + (size_t)(rowBase + gr) * K + gs;
    const __half* gB = B + (size_t)(colBase + gr) * K + gs;
    const size_t rowHop = (size_t)64 * K;
    const uint32_t dA = (uint32_t)gr * 80 + (tid & 3) * 16;
    const uint32_t dB = OPB + dA;

    // ---- ldmatrix offsets ----
    const int quad = lane >> 3, lr = lane & 7;
    uint32_t aOff[4], bOff[2];
    #pragma unroll
    for (int mt = 0; mt < 4; mt++) {
        int r = wm * 64 + mt * 16 + (quad & 1) * 8 + lr;
        aOff[mt] = (uint32_t)(r * RSH + (quad >> 1) * 8) * 2;
    }
    #pragma unroll
    for (int p = 0; p < 2; p++) {
        int r = wn * 32 + p * 16 + (quad & 1) * 8 + lr;
        bOff[p] = OPB + (uint32_t)(r * RSH + (quad >> 1) * 8) * 2;
    }

    float acc[4][4][4];
    #pragma unroll
    for (int i = 0; i < 4; i++)
        #pragma unroll
        for (int j = 0; j < 4; j++)
            #pragma unroll
            for (int e = 0; e < 4; e++) acc[i][j][e] = 0.f;

    // ---- prologue ----
    #pragma unroll
    for (int s = 0; s < NST - 1; s++) {
        const uint32_t d = sbase + s * SS;
        const int k0 = s * BK;
        cp16(d + dA,            gA + k0);
        cp16(d + dA + 64 * 80,  gA + rowHop + k0);
        cp16(d + dB,            gB + k0);
        cp16(d + dB + 64 * 80,  gB + rowHop + k0);
        cp_commit();
    }

    // ---- main loop ----
    for (int it = 0; it < nk; it++) {
        cp_wait2();
        __syncthreads();

        if (it + NST - 1 < nk) {
            const uint32_t d = sbase + ((it + NST - 1) & (NST - 1)) * SS;
            const int k0 = (it + NST - 1) * BK;
            cp16(d + dA,            gA + k0);
            cp16(d + dA + 64 * 80,  gA + rowHop + k0);
            cp16(d + dB,            gB + k0);
            cp16(d + dB + 64 * 80,  gB + rowHop + k0);
        }
        cp_commit();

        const uint32_t st = sbase + (it & (NST - 1)) * SS;
        #pragma unroll
        for (int kk = 0; kk < 2; kk++) {
            const uint32_t ko = kk * 32;     // 16 halves = 32 B
            uint32_t a[4][4], b[2][4];
            #pragma unroll
            for (int mt = 0; mt < 4; mt++) ldsm4(a[mt], st + aOff[mt] + ko);
            #pragma unroll
            for (int p = 0; p < 2; p++)    ldsm4(b[p],  st + bOff[p] + ko);
            #pragma unroll
            for (int mt = 0; mt < 4; mt++)
                #pragma unroll
                for (int p = 0; p < 2; p++) {
                    mma_f16(acc[mt][2*p],   a[mt], b[p][0], b[p][2]);
                    mma_f16(acc[mt][2*p+1], a[mt], b[p][1], b[p][3]);
                }
        }
        __syncthreads();
    }

    // ---- epilogue ----
    const int g = lane >> 2, tg = lane & 3;
    #pragma unroll
    for (int mt = 0; mt < 4; mt++) {
        const int r0 = rowBase + wm * 64 + mt * 16 + g;
        float sc0 = 1.f, sc1 = 1.f;
        if (MODE == 0) {
            sc0 = alpha * row_scale[r0];
            sc1 = alpha * row_scale[r0 + 8];
        }
        #pragma unroll
        for (int nt = 0; nt < 4; nt++) {
            const int c = colBase + wn * 32 + nt * 8 + tg * 2;
            float v0 = acc[mt][nt][0], v1 = acc[mt][nt][1];
            float v2 = acc[mt][nt][2], v3 = acc[mt][nt][3];
            if (MODE == 0) {
                float* C = (float*)Cv;
                *(float2*)&C[(size_t)r0 * N + c]       = make_float2(v0 * sc0, v1 * sc0);
                *(float2*)&C[(size_t)(r0 + 8) * N + c] = make_float2(v2 * sc1, v3 * sc1);
            } else {
                if (MODE == 2) {
                    v0 = __expf(alpha * v0); v1 = __expf(alpha * v1);
                    v2 = __expf(alpha * v2); v3 = __expf(alpha * v3);
                }
                __half* C = (__half*)Cv;
                *(__half2*)&C[(size_t)r0 * N + c]       = __floats2half2_rn(v0, v1);
                *(__half2*)&C[(size_t)(r0 + 8) * N + c] = __floats2half2_rn(v2, v3);
            }
        }
    }
}

// =================== transposes ===================
__global__ void transpose_f2h(const float* __restrict__ in, __half* __restrict__ out, int R, int C)
{
    __shared__ float t[32][33];
    const int c0 = blockIdx.x * 32, r0 = blockIdx.y * 32;
    const int x = threadIdx.x, y = threadIdx.y;
    #pragma unroll
    for (int j = 0; j < 32; j += 8)
        t[y + j][x] = in[(size_t)(r0 + y + j) * C + c0 + x];
    __syncthreads();
    #pragma unroll
    for (int j = 0; j < 32; j += 8)
        out[(size_t)(c0 + y + j) * R + r0 + x] = __float2half_rn(t[x][y + j]);
}
__global__ void transpose_h2h(const __half* __restrict__ in, __half* __restrict__ out, int R, int C)
{
    __shared__ __half t[32][34];
    const int c0 = blockIdx.x * 32, r0 = blockIdx.y * 32;
    const int x = threadIdx.x, y = threadIdx.y;
    #pragma unroll
    for (int j = 0; j < 32; j += 8)
        t[y + j][x] = in[(size_t)(r0 + y + j) * C + c0 + x];
    __syncthreads();
    #pragma unroll
    for (int j = 0; j < 32; j += 8)
        out[(size_t)(c0 + y + j) * R + r0 + x] = t[x][y + j];
}

// =================== round x -> fp16 ===================
__global__ __launch_bounds__(256)
void round_h(const float* __restrict__ in, __half* __restrict__ out, int n4)
{
    int i = blockIdx.x * 256 + threadIdx.x;
    if (i < n4) {
        float4 v = ((const float4*)in)[i];
        __half2* o = (__half2*)(out + (size_t)i * 4);
        o[0] = __floats2half2_rn(v.x, v.y);
        o[1] = __floats2half2_rn(v.z, v.w);
    }
}

// =================== row sums of fp16 P -> 1/sum (fp32) ===================
__global__ __launch_bounds__(256)
void rowsum_inv(const __half* __restrict__ P, float* __restrict__ rinv)
{
    const int tid = threadIdx.x;
    const uint4* p = (const uint4*)(P + (size_t)blockIdx.x * N_TOK);
    float s = 0.f;
    for (int i = tid; i < N_TOK / 8; i += 256) {
        uint4 u = p[i];
        float2 a = __half22float2(*(__half2*)&u.x);
        float2 b = __half22float2(*(__half2*)&u.y);
        float2 c = __half22float2(*(__half2*)&u.z);
        float2 d = __half22float2(*(__half2*)&u.w);
        s += (a.x + a.y) + (b.x + b.y) + (c.x + c.y) + (d.x + d.y);
    }
    #pragma unroll
    for (int o = 16; o; o >>= 1) s += __shfl_xor_sync(0xffffffffu, s, o);
    __shared__ float sh[8];
    if ((tid & 31) == 0) sh[tid >> 5] = s;
    __syncthreads();
    if (tid == 0) {
        float t = 0.f;
        #pragma unroll
        for (int w = 0; w < 8; w++) t += sh[w];
        rinv[blockIdx.x] = 1.0f / t;
    }
}

// =================== host ===================
extern "C" void kernel_launch(void* const* d_in, const int* in_sizes, int n_in,
                              void* d_out, int out_size)
{
    const float* x  = (const float*)d_in[0];
    const float* Wq = (const float*)d_in[1];
    const float* Wk = (const float*)d_in[2];
    const float* Wv = (const float*)d_in[3];
    float* out = (float*)d_out;

    __half *X, *Q, *K, *V, *VT, *WT, *S;
    float *Rinv;
    cudaGetSymbolAddress((void**)&X,    g_X);
    cudaGetSymbolAddress((void**)&Q,    g_Q);
    cudaGetSymbolAddress((void**)&K,    g_K);
    cudaGetSymbolAddress((void**)&V,    g_V);
    cudaGetSymbolAddress((void**)&VT,   g_VT);
    cudaGetSymbolAddress((void**)&WT,   g_WT);
    cudaGetSymbolAddress((void**)&S,    g_S);
    cudaGetSymbolAddress((void**)&Rinv, g_rinv);
    __half* WkT = WT;
    __half* WqT = WT + (size_t)DIM * DIM;
    __half* WvT = WT + (size_t)2 * DIM * DIM;

    cudaFuncSetAttribute(gemm_h<0>, cudaFuncAttributeMaxDynamicSharedMemorySize, SMEM_BYTES);
    cudaFuncSetAttribute(gemm_h<1>, cudaFuncAttributeMaxDynamicSharedMemorySize, SMEM_BYTES);
    cudaFuncSetAttribute(gemm_h<2>, cudaFuncAttributeMaxDynamicSharedMemorySize, SMEM_BYTES);

    const dim3 tblk(32, 8);

    // prep: x -> fp16; W -> fp16 transposed ([in,out] -> [out,in])
    round_h<<<(N_TOK * DIM / 4 + 255) / 256, 256>>>(x, X, N_TOK * DIM / 4);
    transpose_f2h<<<dim3(32, 32), tblk>>>(Wk, WkT, DIM, DIM);
    transpose_f2h<<<dim3(32, 32), tblk>>>(Wq, WqT, DIM, DIM);
    transpose_f2h<<<dim3(32, 32), tblk>>>(Wv, WvT, DIM, DIM);

    const dim3 gProj(DIM / BN, N_TOK / BM);     // (8, 64)
    const dim3 gScore(N_TOK / BN, N_TOK / BM);  // (64, 64)

    // reference name-swap: q = x@Wk, k = x@Wq, v = x@Wv
    gemm_h<1><<<gProj, 256, SMEM_BYTES>>>(X, WkT, Q, N_TOK, DIM, DIM, 1.f, nullptr);
    gemm_h<1><<<gProj, 256, SMEM_BYTES>>>(X, WqT, K, N_TOK, DIM, DIM, 1.f, nullptr);
    gemm_h<1><<<gProj, 256, SMEM_BYTES>>>(X, WvT, V, N_TOK, DIM, DIM, 1.f, nullptr);

    // V^T for PV GEMM B operand
    transpose_h2h<<<dim3(DIM / 32, N_TOK / 32), tblk>>>(V, VT, N_TOK, DIM);

    // P = exp(QK^T / 32) fused in epilogue, stored fp16
    gemm_h<2><<<gScore, 256, SMEM_BYTES>>>(Q, K, S, N_TOK, N_TOK, DIM, 0.03125f, nullptr);

    // rinv = 1 / rowsum(P)
    rowsum_inv<<<N_TOK, 256>>>(S, Rinv);

    // out = diag(rinv) * P @ V
    gemm_h<0><<<gProj, 256, SMEM_BYTES>>>(S, VT, out, N_TOK, DIM, N_TOK, 1.f, Rinv);
}